// round 6
// baseline (speedup 1.0000x reference)
#include <cuda_runtime.h>
#include <cstdint>
#include <cstddef>

#define NE 8
#define NC 4096
#define NM 1024
#define NH 4096
#define NO 1024

// Intermediate h = relu(x@W1^T+b1): [E, C, H] fp32 (512 MB scratch, no alloc allowed)
__device__ float g_hbuf[(size_t)NE * NC * NH];

static __device__ __forceinline__ uint32_t f2tf32(float f) {
    uint32_t u;
    asm("cvt.rna.tf32.f32 %0, %1;" : "=r"(u) : "f"(f));
    return u;
}

// D[row, n] = sum_k A[row,k] * B(k,n) + bias[n] (optional ReLU)
// A: row-major [Mrows x K].
// B_KMAJOR=true : B(k,n) = Bg[n*K + k]    ([N,K] row-major; GEMM1 weights)
// B_KMAJOR=false: B(k,n) = Bg[k*Ntot + n] ([K,N] row-major; GEMM2 weights)
//
// CTA tile 128(M) x 256(N), K-step 32, double-buffered smem (1 sync/k-tile).
// 8 warps in 2(m) x 4(n), warp tile 64x64: per k=8 step, 32 LDS feed 32 MMAs.
template <bool B_KMAJOR, bool RELU>
__global__ __launch_bounds__(256, 1)
void ffn_gemm_v2(const float* __restrict__ Ag, const float* __restrict__ Bg,
                 const float* __restrict__ biasg, float* __restrict__ Dg,
                 int K, int Ntot,
                 size_t sA, size_t sB, size_t sBias, size_t sD)
{
    extern __shared__ uint32_t smdyn[];
    // A buffers: [128][36] words each (stride 36: frag bank = 4u+v, bijective)
    // B k-major: [256][36]  (same property)
    // B row-major: [32][264] (264 % 32 == 8: frag bank = 8v+u, bijective)
    constexpr int AW = 128 * 36;                       // 4608 words
    constexpr int BW = B_KMAJOR ? 256 * 36 : 32 * 264; // 9216 / 8448 words
    uint32_t* Asb[2] = { smdyn,            smdyn + AW };
    uint32_t* Bsb[2] = { smdyn + 2 * AW,   smdyn + 2 * AW + BW };

    const int tid  = threadIdx.x;
    const int lane = tid & 31;
    const int warp = tid >> 5;
    const int wm   = warp >> 2;   // 0..1 -> m offset wm*64
    const int wn   = warp & 3;    // 0..3 -> n offset wn*64
    const int u    = lane >> 2;   // 0..7
    const int v    = lane & 3;    // 0..3

    const int e  = blockIdx.z;
    const int mb = blockIdx.y * 128;
    const int nb = blockIdx.x * 256;

    const float* A    = Ag + (size_t)e * sA;
    const float* B    = Bg + (size_t)e * sB;
    const float* bias = biasg + (size_t)e * sBias + nb;
    float*       D    = Dg + (size_t)e * sD;

    float acc[4][8][4];
    #pragma unroll
    for (int a = 0; a < 4; a++)
        #pragma unroll
        for (int b = 0; b < 8; b++)
            #pragma unroll
            for (int c = 0; c < 4; c++)
                acc[a][b][c] = 0.0f;

    // Staging thread mappings
    const int r0  = tid >> 3;          // 0..31 (row within 32-row slab)
    const int c4  = (tid & 7) << 2;    // k offset {0,4,...,28}
    const int kb0 = tid >> 5;          // 0..7  (rowmajor-B: k = i*8 + kb0)
    const int n4  = lane << 2;         // rowmajor-B: n offset {0..124}

    const int T = K >> 5;

    // ---- prologue: tile 0 -> buffer 0 ----
    {
        #pragma unroll
        for (int i = 0; i < 4; i++) {
            float4 a4 = *(const float4*)(A + (size_t)(mb + i * 32 + r0) * K + c4);
            uint4 t; t.x = f2tf32(a4.x); t.y = f2tf32(a4.y); t.z = f2tf32(a4.z); t.w = f2tf32(a4.w);
            *(uint4*)&Asb[0][(i * 32 + r0) * 36 + c4] = t;
        }
        if (B_KMAJOR) {
            #pragma unroll
            for (int i = 0; i < 8; i++) {
                float4 b4 = *(const float4*)(B + (size_t)(nb + i * 32 + r0) * K + c4);
                uint4 t; t.x = f2tf32(b4.x); t.y = f2tf32(b4.y); t.z = f2tf32(b4.z); t.w = f2tf32(b4.w);
                *(uint4*)&Bsb[0][(i * 32 + r0) * 36 + c4] = t;
            }
        } else {
            #pragma unroll
            for (int i = 0; i < 4; i++)
                #pragma unroll
                for (int j = 0; j < 2; j++) {
                    float4 b4 = *(const float4*)(B + (size_t)(i * 8 + kb0) * Ntot + nb + j * 128 + n4);
                    uint4 t; t.x = f2tf32(b4.x); t.y = f2tf32(b4.y); t.z = f2tf32(b4.z); t.w = f2tf32(b4.w);
                    *(uint4*)&Bsb[0][(i * 8 + kb0) * 264 + j * 128 + n4] = t;
                }
        }
    }
    __syncthreads();

    // ---- mainloop: prefetch(t+1) -> MMA(buf p) -> STS(buf 1-p) -> sync ----
    for (int t = 0; t < T; t++) {
        const int p = t & 1;
        const bool pf = (t + 1 < T);
        float4 aR[4], bR[8];

        if (pf) {
            const int k0 = (t + 1) << 5;
            #pragma unroll
            for (int i = 0; i < 4; i++)
                aR[i] = *(const float4*)(A + (size_t)(mb + i * 32 + r0) * K + k0 + c4);
            if (B_KMAJOR) {
                #pragma unroll
                for (int i = 0; i < 8; i++)
                    bR[i] = *(const float4*)(B + (size_t)(nb + i * 32 + r0) * K + k0 + c4);
            } else {
                #pragma unroll
                for (int i = 0; i < 4; i++)
                    #pragma unroll
                    for (int j = 0; j < 2; j++)
                        bR[i * 2 + j] = *(const float4*)(B + (size_t)(k0 + i * 8 + kb0) * Ntot + nb + j * 128 + n4);
            }
        }

        const uint32_t* __restrict__ As = Asb[p];
        const uint32_t* __restrict__ Bs = Bsb[p];

        #pragma unroll
        for (int kk = 0; kk < 32; kk += 8) {
            uint32_t af[4][4];
            uint32_t bf[8][2];
            #pragma unroll
            for (int tm = 0; tm < 4; tm++) {
                const int ia = (wm * 64 + tm * 16 + u) * 36 + kk + v;
                af[tm][0] = As[ia];
                af[tm][1] = As[ia + 8 * 36];
                af[tm][2] = As[ia + 4];
                af[tm][3] = As[ia + 8 * 36 + 4];
            }
            #pragma unroll
            for (int tn = 0; tn < 8; tn++) {
                const int nn = wn * 64 + tn * 8 + u;
                if (B_KMAJOR) {
                    const int ib = nn * 36 + kk + v;
                    bf[tn][0] = Bs[ib];
                    bf[tn][1] = Bs[ib + 4];
                } else {
                    const int ib = (kk + v) * 264 + nn;
                    bf[tn][0] = Bs[ib];
                    bf[tn][1] = Bs[ib + 4 * 264];
                }
            }
            #pragma unroll
            for (int tm = 0; tm < 4; tm++)
                #pragma unroll
                for (int tn = 0; tn < 8; tn++) {
                    float* c = acc[tm][tn];
                    asm volatile(
                        "mma.sync.aligned.m16n8k8.row.col.f32.tf32.tf32.f32 "
                        "{%0,%1,%2,%3}, {%4,%5,%6,%7}, {%8,%9}, {%0,%1,%2,%3};\n"
                        : "+f"(c[0]), "+f"(c[1]), "+f"(c[2]), "+f"(c[3])
                        : "r"(af[tm][0]), "r"(af[tm][1]), "r"(af[tm][2]), "r"(af[tm][3]),
                          "r"(bf[tn][0]), "r"(bf[tn][1]));
                }
        }

        if (pf) {
            uint32_t* An = Asb[1 - p];
            uint32_t* Bn = Bsb[1 - p];
            #pragma unroll
            for (int i = 0; i < 4; i++) {
                uint4 t; t.x = f2tf32(aR[i].x); t.y = f2tf32(aR[i].y);
                t.z = f2tf32(aR[i].z); t.w = f2tf32(aR[i].w);
                *(uint4*)&An[(i * 32 + r0) * 36 + c4] = t;
            }
            if (B_KMAJOR) {
                #pragma unroll
                for (int i = 0; i < 8; i++) {
                    uint4 t; t.x = f2tf32(bR[i].x); t.y = f2tf32(bR[i].y);
                    t.z = f2tf32(bR[i].z); t.w = f2tf32(bR[i].w);
                    *(uint4*)&Bn[(i * 32 + r0) * 36 + c4] = t;
                }
            } else {
                #pragma unroll
                for (int i = 0; i < 4; i++)
                    #pragma unroll
                    for (int j = 0; j < 2; j++) {
                        float4 b4 = bR[i * 2 + j];
                        uint4 t; t.x = f2tf32(b4.x); t.y = f2tf32(b4.y);
                        t.z = f2tf32(b4.z); t.w = f2tf32(b4.w);
                        *(uint4*)&Bn[(i * 8 + kb0) * 264 + j * 128 + n4] = t;
                    }
            }
        }
        __syncthreads();
    }

    // ---- epilogue: bias (+ReLU), fp32 out ----
    #pragma unroll
    for (int tm = 0; tm < 4; tm++) {
        const int row = mb + wm * 64 + tm * 16 + u;
        #pragma unroll
        for (int tn = 0; tn < 8; tn++) {
            const int col = nb + wn * 64 + tn * 8 + 2 * v;
            const float2 bv = *(const float2*)&bias[wn * 64 + tn * 8 + 2 * v];
            float x0 = acc[tm][tn][0] + bv.x;
            float x1 = acc[tm][tn][1] + bv.y;
            float x2 = acc[tm][tn][2] + bv.x;
            float x3 = acc[tm][tn][3] + bv.y;
            if (RELU) {
                x0 = fmaxf(x0, 0.0f); x1 = fmaxf(x1, 0.0f);
                x2 = fmaxf(x2, 0.0f); x3 = fmaxf(x3, 0.0f);
            }
            *(float2*)&D[(size_t)row * Ntot + col]       = make_float2(x0, x1);
            *(float2*)&D[(size_t)(row + 8) * Ntot + col] = make_float2(x2, x3);
        }
    }
}

extern "C" void kernel_launch(void* const* d_in, const int* in_sizes, int n_in,
                              void* d_out, int out_size)
{
    const float* x     = (const float*)d_in[0];   // [E, C, M]
    const float* fc1_w = (const float*)d_in[1];   // [E, H, M]  ([N,K] k-major)
    const float* fc1_b = (const float*)d_in[2];   // [E, H]
    const float* fc2_w = (const float*)d_in[3];   // [E, H, O]  ([K,N] row-major)
    const float* fc2_b = (const float*)d_in[4];   // [E, O]
    float* out = (float*)d_out;                   // [E, C, O]

    float* hb = nullptr;
    cudaGetSymbolAddress((void**)&hb, g_hbuf);

    // smem: A 2*4608 words; B kmajor 2*9216 words -> 110,592 B; rowmajor -> 104,448 B
    const int SM1 = (2 * 128 * 36 + 2 * 256 * 36) * 4;
    const int SM2 = (2 * 128 * 36 + 2 * 32 * 264) * 4;
    cudaFuncSetAttribute((const void*)ffn_gemm_v2<true, true>,
                         cudaFuncAttributeMaxDynamicSharedMemorySize, SM1);
    cudaFuncSetAttribute((const void*)ffn_gemm_v2<false, false>,
                         cudaFuncAttributeMaxDynamicSharedMemorySize, SM2);

    // GEMM1: h = relu(x @ fc1_w^T + b1)   M-rows=C, N=H, K=M
    ffn_gemm_v2<true, true><<<dim3(NH / 256, NC / 128, NE), 256, SM1>>>(
        x, fc1_w, fc1_b, hb,
        NM, NH,
        (size_t)NC * NM, (size_t)NH * NM, (size_t)NH, (size_t)NC * NH);

    // GEMM2: y = h @ fc2_w + b2           M-rows=C, N=O, K=H
    ffn_gemm_v2<false, false><<<dim3(NO / 256, NC / 128, NE), 256, SM2>>>(
        hb, fc2_w, fc2_b, out,
        NH, NO,
        (size_t)NC * NH, (size_t)NH * NO, (size_t)NO, (size_t)NC * NO);
}

// round 7
// speedup vs baseline: 1.0778x; 1.0778x over previous
#include <cuda_runtime.h>
#include <cstdint>
#include <cstddef>

#define NE 8
#define NC 4096
#define NM 1024
#define NH 4096
#define NO 1024

// Scratch (no allocs allowed):
__device__ float g_hbuf[(size_t)NE * NC * NH];   // h, stored pre-rounded to tf32
__device__ float g_xr [(size_t)NE * NC * NM];    // x  pre-rounded
__device__ float g_w1r[(size_t)NE * NH * NM];    // fc1_w pre-rounded
__device__ float g_w2r[(size_t)NE * NH * NO];    // fc2_w pre-rounded

static __device__ __forceinline__ uint32_t f2tf32(float f) {
    uint32_t u;
    asm("cvt.rna.tf32.f32 %0, %1;" : "=r"(u) : "f"(f));
    return u;
}
static __device__ __forceinline__ void cpa16(uint32_t dst, const float* src) {
    asm volatile("cp.async.cg.shared.global [%0], [%1], 16;" :: "r"(dst), "l"(src));
}

// Elementwise tf32 pre-round (rna), float4-vectorized
__global__ __launch_bounds__(256)
void round_tf32_kernel(const float4* __restrict__ in, float4* __restrict__ out, size_t n4) {
    size_t i = (size_t)blockIdx.x * blockDim.x + threadIdx.x;
    size_t stride = (size_t)gridDim.x * blockDim.x;
    for (; i < n4; i += stride) {
        float4 v = in[i];
        float4 o;
        o.x = __uint_as_float(f2tf32(v.x));
        o.y = __uint_as_float(f2tf32(v.y));
        o.z = __uint_as_float(f2tf32(v.z));
        o.w = __uint_as_float(f2tf32(v.w));
        out[i] = o;
    }
}

// D[row, n] = sum_k A[row,k] * B(k,n) + bias[n]  (RELU_CVT: relu + tf32-round the output)
// A: row-major [Mrows x K] (already tf32-rounded values).
// B_KMAJOR=true : B(k,n) = Bg[n*K + k]    ([N,K]; GEMM1 weights)
// B_KMAJOR=false: B(k,n) = Bg[k*Ntot + n] ([K,N]; GEMM2 weights)
//
// CTA tile 128x128, K-step 32, DOUBLE-buffered smem fed by cp.async (no register
// staging, no cvt in loop, 1 syncthreads per k-tile). 8 warps 2(m)x4(n), warp 64x32.
template <bool B_KMAJOR, bool RELU_CVT>
__global__ __launch_bounds__(256, 2)
void ffn_gemm_v3(const float* __restrict__ Ag, const float* __restrict__ Bg,
                 const float* __restrict__ biasg, float* __restrict__ Dg,
                 int K, int Ntot,
                 size_t sA, size_t sB, size_t sBias, size_t sD)
{
    extern __shared__ uint32_t smdyn[];
    // A: [128][36] words (pad: frag bank = 4u+v bijective)
    // B k-major: [128][36]; B row-major: [32][136] (136%32==8: frag bank 8v+u bijective)
    constexpr int AW = 128 * 36;                       // 4608 words
    constexpr int BW = B_KMAJOR ? 128 * 36 : 32 * 136; // 4608 / 4352 words
    uint32_t* Asb[2] = { smdyn,          smdyn + AW };
    uint32_t* Bsb[2] = { smdyn + 2 * AW, smdyn + 2 * AW + BW };

    const int tid  = threadIdx.x;
    const int lane = tid & 31;
    const int warp = tid >> 5;
    const int wm   = warp >> 2;   // 0..1 -> m offset wm*64
    const int wn   = warp & 3;    // 0..3 -> n offset wn*32
    const int u    = lane >> 2;   // 0..7
    const int v    = lane & 3;    // 0..3

    const int e  = blockIdx.z;
    const int mb = blockIdx.y * 128;
    const int nb = blockIdx.x * 128;

    const float* A    = Ag + (size_t)e * sA;
    const float* B    = Bg + (size_t)e * sB;
    const float* bias = biasg + (size_t)e * sBias;
    float*       D    = Dg + (size_t)e * sD;

    float acc[4][4][4];
    #pragma unroll
    for (int a = 0; a < 4; a++)
        #pragma unroll
        for (int b = 0; b < 4; b++)
            #pragma unroll
            for (int c = 0; c < 4; c++)
                acc[a][b][c] = 0.0f;

    // Staging mappings (256 threads)
    const int r0  = tid >> 3;          // 0..31
    const int c4  = (tid & 7) << 2;    // {0,4,...,28}
    const int kb0 = tid >> 5;          // 0..7   (rowmajor-B k row)
    const int n4  = lane << 2;         // 0..124 (rowmajor-B n offset)

    // Precomputed global base pointers for staging
    const float* Apt = A + (size_t)(mb + r0) * K + c4;
    const float* Bpt = B_KMAJOR ? (B + (size_t)(nb + r0) * K + c4)
                                : (B + (size_t)kb0 * Ntot + nb + n4);

    const int T = K >> 5;

    // stage k-tile into buffer b (8 cp.async of 16B per thread)
    auto stage = [&](int b, int k0) {
        uint32_t abase = (uint32_t)__cvta_generic_to_shared(Asb[b]);
        uint32_t bbase = (uint32_t)__cvta_generic_to_shared(Bsb[b]);
        #pragma unroll
        for (int i = 0; i < 4; i++)
            cpa16(abase + ((i * 32 + r0) * 36 + c4) * 4, Apt + (size_t)(i * 32) * K + k0);
        if (B_KMAJOR) {
            #pragma unroll
            for (int i = 0; i < 4; i++)
                cpa16(bbase + ((i * 32 + r0) * 36 + c4) * 4, Bpt + (size_t)(i * 32) * K + k0);
        } else {
            #pragma unroll
            for (int i = 0; i < 4; i++)
                cpa16(bbase + ((i * 8 + kb0) * 136 + n4) * 4, Bpt + (size_t)(k0 + i * 8) * Ntot);
        }
    };

    // ---- prologue ----
    stage(0, 0);
    asm volatile("cp.async.commit_group;" ::: "memory");
    asm volatile("cp.async.wait_group 0;" ::: "memory");
    __syncthreads();

    // ---- mainloop ----
    for (int t = 0; t < T; t++) {
        const int p = t & 1;
        if (t + 1 < T) {
            stage(1 - p, (t + 1) << 5);
            asm volatile("cp.async.commit_group;" ::: "memory");
        }

        const uint32_t* __restrict__ As = Asb[p];
        const uint32_t* __restrict__ Bs = Bsb[p];
        #pragma unroll
        for (int kk = 0; kk < 32; kk += 8) {
            uint32_t af[4][4];
            uint32_t bf[4][2];
            #pragma unroll
            for (int tm = 0; tm < 4; tm++) {
                const int ia = (wm * 64 + tm * 16 + u) * 36 + kk + v;
                af[tm][0] = As[ia];
                af[tm][1] = As[ia + 8 * 36];
                af[tm][2] = As[ia + 4];
                af[tm][3] = As[ia + 8 * 36 + 4];
            }
            #pragma unroll
            for (int tn = 0; tn < 4; tn++) {
                const int nn = wn * 32 + tn * 8 + u;
                if (B_KMAJOR) {
                    const int ib = nn * 36 + kk + v;
                    bf[tn][0] = Bs[ib];
                    bf[tn][1] = Bs[ib + 4];
                } else {
                    const int ib = (kk + v) * 136 + nn;
                    bf[tn][0] = Bs[ib];
                    bf[tn][1] = Bs[ib + 4 * 136];
                }
            }
            #pragma unroll
            for (int tm = 0; tm < 4; tm++)
                #pragma unroll
                for (int tn = 0; tn < 4; tn++) {
                    float* c = acc[tm][tn];
                    asm volatile(
                        "mma.sync.aligned.m16n8k8.row.col.f32.tf32.tf32.f32 "
                        "{%0,%1,%2,%3}, {%4,%5,%6,%7}, {%8,%9}, {%0,%1,%2,%3};\n"
                        : "+f"(c[0]), "+f"(c[1]), "+f"(c[2]), "+f"(c[3])
                        : "r"(af[tm][0]), "r"(af[tm][1]), "r"(af[tm][2]), "r"(af[tm][3]),
                          "r"(bf[tn][0]), "r"(bf[tn][1]));
                }
        }

        if (t + 1 < T)
            asm volatile("cp.async.wait_group 0;" ::: "memory");
        __syncthreads();
    }

    // ---- epilogue ----
    #pragma unroll
    for (int tm = 0; tm < 4; tm++) {
        const int row = mb + wm * 64 + tm * 16 + u;
        #pragma unroll
        for (int tn = 0; tn < 4; tn++) {
            const int col = nb + wn * 32 + tn * 8 + 2 * v;
            const float2 bv = *(const float2*)&bias[col];
            float x0 = acc[tm][tn][0] + bv.x;
            float x1 = acc[tm][tn][1] + bv.y;
            float x2 = acc[tm][tn][2] + bv.x;
            float x3 = acc[tm][tn][3] + bv.y;
            if (RELU_CVT) {
                // relu then tf32-round: GEMM2 then consumes h with no in-loop cvt,
                // bit-identical to staging-time cvt.
                x0 = __uint_as_float(f2tf32(fmaxf(x0, 0.0f)));
                x1 = __uint_as_float(f2tf32(fmaxf(x1, 0.0f)));
                x2 = __uint_as_float(f2tf32(fmaxf(x2, 0.0f)));
                x3 = __uint_as_float(f2tf32(fmaxf(x3, 0.0f)));
            }
            *(float2*)&D[(size_t)row * Ntot + col]       = make_float2(x0, x1);
            *(float2*)&D[(size_t)(row + 8) * Ntot + col] = make_float2(x2, x3);
        }
    }
}

extern "C" void kernel_launch(void* const* d_in, const int* in_sizes, int n_in,
                              void* d_out, int out_size)
{
    const float* x     = (const float*)d_in[0];   // [E, C, M]
    const float* fc1_w = (const float*)d_in[1];   // [E, H, M]  ([N,K] k-major)
    const float* fc1_b = (const float*)d_in[2];   // [E, H]
    const float* fc2_w = (const float*)d_in[3];   // [E, H, O]  ([K,N] row-major)
    const float* fc2_b = (const float*)d_in[4];   // [E, O]
    float* out = (float*)d_out;                   // [E, C, O]

    float *hb = nullptr, *xr = nullptr, *w1r = nullptr, *w2r = nullptr;
    cudaGetSymbolAddress((void**)&hb,  g_hbuf);
    cudaGetSymbolAddress((void**)&xr,  g_xr);
    cudaGetSymbolAddress((void**)&w1r, g_w1r);
    cudaGetSymbolAddress((void**)&w2r, g_w2r);

    // 0) pre-round x / fc1_w / fc2_w to tf32 (rna) once
    {
        const size_t nx  = (size_t)NE * NC * NM / 4;
        const size_t nw1 = (size_t)NE * NH * NM / 4;
        const size_t nw2 = (size_t)NE * NH * NO / 4;
        round_tf32_kernel<<<4096, 256>>>((const float4*)x,     (float4*)xr,  nx);
        round_tf32_kernel<<<4096, 256>>>((const float4*)fc1_w, (float4*)w1r, nw1);
        round_tf32_kernel<<<4096, 256>>>((const float4*)fc2_w, (float4*)w2r, nw2);
    }

    const int SM1 = (2 * 128 * 36 + 2 * 128 * 36) * 4;   // 73,728 B
    const int SM2 = (2 * 128 * 36 + 2 * 32 * 136) * 4;   // 71,680 B
    cudaFuncSetAttribute((const void*)ffn_gemm_v3<true, true>,
                         cudaFuncAttributeMaxDynamicSharedMemorySize, SM1);
    cudaFuncSetAttribute((const void*)ffn_gemm_v3<false, false>,
                         cudaFuncAttributeMaxDynamicSharedMemorySize, SM2);

    // 1) h = relu(x @ fc1_w^T + b1), stored tf32-rounded   M-rows=C, N=H, K=M
    ffn_gemm_v3<true, true><<<dim3(NH / 128, NC / 128, NE), 256, SM1>>>(
        xr, w1r, fc1_b, hb,
        NM, NH,
        (size_t)NC * NM, (size_t)NH * NM, (size_t)NH, (size_t)NC * NH);

    // 2) y = h @ fc2_w + b2                                M-rows=C, N=O, K=H
    ffn_gemm_v3<false, false><<<dim3(NO / 128, NC / 128, NE), 256, SM2>>>(
        hb, w2r, fc2_b, out,
        NH, NO,
        (size_t)NC * NH, (size_t)NH * NO, (size_t)NO, (size_t)NC * NO);
}

// round 13
// speedup vs baseline: 1.3390x; 1.2424x over previous
#include <cuda_runtime.h>
#include <cstdint>
#include <cstddef>

#define NE 8
#define NC 4096
#define NM 1024
#define NH 4096
#define NO 1024

// Scratch (no allocs allowed):
__device__ float g_hbuf[(size_t)NE * NC * NH];   // h, stored tf32-pre-rounded
__device__ float g_xr [(size_t)NE * NC * NM];    // x pre-rounded
__device__ float g_w1r[(size_t)NE * NH * NM];    // fc1_w pre-rounded
__device__ float g_w2t[(size_t)NE * NO * NH];    // fc2_w transposed [O,H] + pre-rounded

static __device__ __forceinline__ uint32_t f2tf32(float f) {
    uint32_t u;
    asm("cvt.rna.tf32.f32 %0, %1;" : "=r"(u) : "f"(f));
    return u;
}
static __device__ __forceinline__ void cpa16(uint32_t dst, const float* src) {
    asm volatile("cp.async.cg.shared.global [%0], [%1], 16;" :: "r"(dst), "l"(src));
}

// Elementwise tf32 pre-round (rna)
__global__ __launch_bounds__(256)
void round_tf32_kernel(const float4* __restrict__ in, float4* __restrict__ out, size_t n4) {
    size_t i = (size_t)blockIdx.x * blockDim.x + threadIdx.x;
    size_t stride = (size_t)gridDim.x * blockDim.x;
    for (; i < n4; i += stride) {
        float4 v = in[i];
        float4 o;
        o.x = __uint_as_float(f2tf32(v.x));
        o.y = __uint_as_float(f2tf32(v.y));
        o.z = __uint_as_float(f2tf32(v.z));
        o.w = __uint_as_float(f2tf32(v.w));
        out[i] = o;
    }
}

// fc2_w [E,H,O] -> [E,O,H], tf32-rounded (so GEMM2 B is K-major like GEMM1)
__global__ __launch_bounds__(256)
void transpose_round_w2(const float* __restrict__ w2, float* __restrict__ w2t) {
    __shared__ float tile[32][33];
    const int e = blockIdx.z;
    const float* src = w2 + (size_t)e * NH * NO;
    float* dst = w2t + (size_t)e * NO * NH;
    const int o0 = blockIdx.x * 32, h0 = blockIdx.y * 32;
    const int tx = threadIdx.x, ty = threadIdx.y;
    #pragma unroll
    for (int i = ty; i < 32; i += 8)
        tile[i][tx] = src[(size_t)(h0 + i) * NO + o0 + tx];
    __syncthreads();
    #pragma unroll
    for (int i = ty; i < 32; i += 8)
        dst[(size_t)(o0 + i) * NH + h0 + tx] =
            __uint_as_float(f2tf32(tile[tx][i]));
}

// D[row,n] = sum_k A[row,k]*B[n,k] + bias[n]  (RELU_CVT: relu + tf32-round output)
// A,B K-major, values already tf32-rounded. CTA tile 128x128, K-step 32,
// double-buffered cp.async. 128 threads = 4 warps in 2(m)x2(n), warp tile 64x64:
// per k=8 step, 32 LDS feed 32 MMAs (128B/MMA crossbar, was 192B/MMA at 64x32).
template <bool RELU_CVT>
__global__ __launch_bounds__(128, 2)
void ffn_gemm_v4(const float* __restrict__ Ag, const float* __restrict__ Bg,
                 const float* __restrict__ biasg, float* __restrict__ Dg,
                 int K, int Ntot,
                 size_t sA, size_t sB, size_t sBias, size_t sD)
{
    extern __shared__ uint32_t smdyn[];
    constexpr int AW = 128 * 36;   // [128 rows][36 words] (pad: frag bank 4u+v bijective)
    uint32_t* Asb[2] = { smdyn,          smdyn + AW };
    uint32_t* Bsb[2] = { smdyn + 2 * AW, smdyn + 3 * AW };

    const int tid  = threadIdx.x;
    const int lane = tid & 31;
    const int warp = tid >> 5;
    const int wm   = warp >> 1;   // 0..1 -> m offset wm*64
    const int wn   = warp & 1;    // 0..1 -> n offset wn*64
    const int u    = lane >> 2;   // 0..7
    const int v    = lane & 3;    // 0..3

    const int e  = blockIdx.z;
    const int mb = blockIdx.y * 128;
    const int nb = blockIdx.x * 128;

    const float* A    = Ag + (size_t)e * sA;
    const float* B    = Bg + (size_t)e * sB;
    const float* bias = biasg + (size_t)e * sBias + nb;
    float*       D    = Dg + (size_t)e * sD;

    float acc[4][8][4];
    #pragma unroll
    for (int a = 0; a < 4; a++)
        #pragma unroll
        for (int b = 0; b < 8; b++)
            #pragma unroll
            for (int c = 0; c < 4; c++)
                acc[a][b][c] = 0.0f;

    // Staging: 128 threads, 8 rows each of A and B per k-tile (16 cp.async/thread)
    const int r0 = tid >> 3;           // 0..15
    const int c4 = (tid & 7) << 2;     // {0,4,...,28}
    const float* Apt = A + (size_t)(mb + r0) * K + c4;
    const float* Bpt = B + (size_t)(nb + r0) * K + c4;

    const int T = K >> 5;

    auto stage = [&](int b, int k0) {
        uint32_t abase = (uint32_t)__cvta_generic_to_shared(Asb[b]);
        uint32_t bbase = (uint32_t)__cvta_generic_to_shared(Bsb[b]);
        #pragma unroll
        for (int i = 0; i < 8; i++)
            cpa16(abase + ((i * 16 + r0) * 36 + c4) * 4, Apt + (size_t)(i * 16) * K + k0);
        #pragma unroll
        for (int i = 0; i < 8; i++)
            cpa16(bbase + ((i * 16 + r0) * 36 + c4) * 4, Bpt + (size_t)(i * 16) * K + k0);
    };

    // ---- prologue ----
    stage(0, 0);
    asm volatile("cp.async.commit_group;" ::: "memory");
    asm volatile("cp.async.wait_group 0;" ::: "memory");
    __syncthreads();

    // ---- mainloop ----
    for (int t = 0; t < T; t++) {
        const int p = t & 1;
        if (t + 1 < T) {
            stage(1 - p, (t + 1) << 5);
            asm volatile("cp.async.commit_group;" ::: "memory");
        }

        const uint32_t* __restrict__ As = Asb[p];
        const uint32_t* __restrict__ Bs = Bsb[p];
        #pragma unroll
        for (int kk = 0; kk < 32; kk += 8) {
            uint32_t af[4][4];
            uint32_t bf[8][2];
            #pragma unroll
            for (int tm = 0; tm < 4; tm++) {
                const int ia = (wm * 64 + tm * 16 + u) * 36 + kk + v;
                af[tm][0] = As[ia];
                af[tm][1] = As[ia + 8 * 36];
                af[tm][2] = As[ia + 4];
                af[tm][3] = As[ia + 8 * 36 + 4];
            }
            #pragma unroll
            for (int tn = 0; tn < 8; tn++) {
                const int ib = (wn * 64 + tn * 8 + u) * 36 + kk + v;
                bf[tn][0] = Bs[ib];
                bf[tn][1] = Bs[ib + 4];
            }
            #pragma unroll
            for (int tm = 0; tm < 4; tm++)
                #pragma unroll
                for (int tn = 0; tn < 8; tn++) {
                    float* c = acc[tm][tn];
                    asm volatile(
                        "mma.sync.aligned.m16n8k8.row.col.f32.tf32.tf32.f32 "
                        "{%0,%1,%2,%3}, {%4,%5,%6,%7}, {%8,%9}, {%0,%1,%2,%3};\n"
                        : "+f"(c[0]), "+f"(c[1]), "+f"(c[2]), "+f"(c[3])
                        : "r"(af[tm][0]), "r"(af[tm][1]), "r"(af[tm][2]), "r"(af[tm][3]),
                          "r"(bf[tn][0]), "r"(bf[tn][1]));
                }
        }

        if (t + 1 < T)
            asm volatile("cp.async.wait_group 0;" ::: "memory");
        __syncthreads();
    }

    // ---- epilogue ----
    #pragma unroll
    for (int tm = 0; tm < 4; tm++) {
        const int row = mb + wm * 64 + tm * 16 + u;
        #pragma unroll
        for (int tn = 0; tn < 8; tn++) {
            const int lc = wn * 64 + tn * 8 + 2 * v;
            const float2 bv = *(const float2*)&bias[lc];
            float x0 = acc[tm][tn][0] + bv.x;
            float x1 = acc[tm][tn][1] + bv.y;
            float x2 = acc[tm][tn][2] + bv.x;
            float x3 = acc[tm][tn][3] + bv.y;
            if (RELU_CVT) {
                x0 = __uint_as_float(f2tf32(fmaxf(x0, 0.0f)));
                x1 = __uint_as_float(f2tf32(fmaxf(x1, 0.0f)));
                x2 = __uint_as_float(f2tf32(fmaxf(x2, 0.0f)));
                x3 = __uint_as_float(f2tf32(fmaxf(x3, 0.0f)));
            }
            *(float2*)&D[(size_t)row * Ntot + nb + lc]       = make_float2(x0, x1);
            *(float2*)&D[(size_t)(row + 8) * Ntot + nb + lc] = make_float2(x2, x3);
        }
    }
}

extern "C" void kernel_launch(void* const* d_in, const int* in_sizes, int n_in,
                              void* d_out, int out_size)
{
    const float* x     = (const float*)d_in[0];   // [E, C, M]
    const float* fc1_w = (const float*)d_in[1];   // [E, H, M]  (K-major)
    const float* fc1_b = (const float*)d_in[2];   // [E, H]
    const float* fc2_w = (const float*)d_in[3];   // [E, H, O]  -> transpose to [E,O,H]
    const float* fc2_b = (const float*)d_in[4];   // [E, O]
    float* out = (float*)d_out;                   // [E, C, O]

    float *hb = nullptr, *xr = nullptr, *w1r = nullptr, *w2t = nullptr;
    cudaGetSymbolAddress((void**)&hb,  g_hbuf);
    cudaGetSymbolAddress((void**)&xr,  g_xr);
    cudaGetSymbolAddress((void**)&w1r, g_w1r);
    cudaGetSymbolAddress((void**)&w2t, g_w2t);

    // 0) pre-round x / fc1_w; transpose+round fc2_w
    round_tf32_kernel<<<4096, 256>>>((const float4*)x,     (float4*)xr,
                                     (size_t)NE * NC * NM / 4);
    round_tf32_kernel<<<4096, 256>>>((const float4*)fc1_w, (float4*)w1r,
                                     (size_t)NE * NH * NM / 4);
    transpose_round_w2<<<dim3(NO / 32, NH / 32, NE), dim3(32, 8)>>>(fc2_w, w2t);

    const int SMB = 4 * 128 * 36 * 4;   // 73,728 B (A0,A1,B0,B1)
    cudaFuncSetAttribute((const void*)ffn_gemm_v4<true>,
                         cudaFuncAttributeMaxDynamicSharedMemorySize, SMB);
    cudaFuncSetAttribute((const void*)ffn_gemm_v4<false>,
                         cudaFuncAttributeMaxDynamicSharedMemorySize, SMB);

    // 1) h = relu(x @ fc1_w^T + b1), stored tf32-rounded   (M=C, N=H, K=M)
    ffn_gemm_v4<true><<<dim3(NH / 128, NC / 128, NE), 128, SMB>>>(
        xr, w1r, fc1_b, hb,
        NM, NH,
        (size_t)NC * NM, (size_t)NH * NM, (size_t)NH, (size_t)NC * NH);

    // 2) y = h @ w2t^T + b2                                (M=C, N=O, K=H)
    ffn_gemm_v4<false><<<dim3(NO / 128, NC / 128, NE), 128, SMB>>>(
        hb, w2t, fc2_b, out,
        NH, NO,
        (size_t)NC * NH, (size_t)NO * NH, (size_t)NO, (size_t)NC * NO);
}